// round 3
// baseline (speedup 1.0000x reference)
#include <cuda_runtime.h>
#include <cuda_bf16.h>
#include <math.h>

// Problem constants
#define BATCH 16
#define SEQ   512
#define HID   768
#define NT    9
#define DIM   64
#define COUT  (NT * 2 * DIM)   // 1152
#define MROWS (BATCH * SEQ)    // 8192

// Scratch (device globals — no allocation allowed in kernel_launch)
__device__ float g_q[BATCH * NT * SEQ * DIM];   // [b,t,s,d]
__device__ float g_k[BATCH * NT * SEQ * DIM];   // [b,t,s,d]
__device__ float g_cs[SEQ * DIM];               // repeated cos table
__device__ float g_sn[SEQ * DIM];               // repeated sin table

// ---------------------------------------------------------------------------
// Kernel 0: RoPE cos/sin tables.  cos_rep[s][d] = cos(s * 10000^{-2*(d/2)/64})
// ---------------------------------------------------------------------------
__global__ void rope_table() {
    int idx = blockIdx.x * blockDim.x + threadIdx.x;   // 0 .. 32767
    if (idx >= SEQ * DIM) return;
    int s = idx >> 6;
    int d = idx & 63;
    int i = d >> 1;
    float inv = powf(10000.0f, -(float)(2 * i) / 64.0f);
    float ang = (float)s * inv;
    g_cs[idx] = cosf(ang);
    g_sn[idx] = sinf(ang);
}

// ---------------------------------------------------------------------------
// Kernel 1: SGEMM  out[8192,1152] = hidden @ W + b, fused RoPE epilogue,
// scatter into g_q / g_k with [b,t,s,d] layout.
// Block tile 64(M) x 64(N), K-tile 16, 256 threads, 4x4 microtile.
// ---------------------------------------------------------------------------
__global__ void __launch_bounds__(256) gemm_rope(
    const float* __restrict__ hidden,
    const float* __restrict__ Wm,
    const float* __restrict__ bias)
{
    __shared__ float A_sm[16][68];   // [k][m]  (transposed)
    __shared__ float B_sm[16][68];   // [k][n]

    const int tid = threadIdx.x;
    const int tx  = tid & 15;
    const int ty  = tid >> 4;
    const int c0   = blockIdx.x * 64;
    const int row0 = blockIdx.y * 64;

    float acc[4][4] = {};

    const int am = tid >> 2;          // 0..63  (A load row)
    const int ak = (tid & 3) * 4;     // 0,4,8,12 (A load k-quad)
    const int bk = tid >> 4;          // 0..15  (B load k)
    const int bc = (tid & 15) * 4;    // B load col-quad

    for (int k0 = 0; k0 < HID; k0 += 16) {
        float4 av = *(const float4*)(hidden + (size_t)(row0 + am) * HID + k0 + ak);
        A_sm[ak + 0][am] = av.x;
        A_sm[ak + 1][am] = av.y;
        A_sm[ak + 2][am] = av.z;
        A_sm[ak + 3][am] = av.w;
        float4 bv = *(const float4*)(Wm + (size_t)(k0 + bk) * COUT + c0 + bc);
        *(float4*)&B_sm[bk][bc] = bv;
        __syncthreads();

        #pragma unroll
        for (int k = 0; k < 16; k++) {
            float4 a4 = *(const float4*)&A_sm[k][ty * 4];
            float4 b4 = *(const float4*)&B_sm[k][tx * 4];
            float a[4] = {a4.x, a4.y, a4.z, a4.w};
            float b[4] = {b4.x, b4.y, b4.z, b4.w};
            #pragma unroll
            for (int i = 0; i < 4; i++)
                #pragma unroll
                for (int j = 0; j < 4; j++)
                    acc[i][j] += a[i] * b[j];
        }
        __syncthreads();
    }

    // Epilogue: bias + RoPE (interleaved pairs), scatter to g_q / g_k.
    const int cbase = c0 + tx * 4;
    #pragma unroll
    for (int i = 0; i < 4; i++) {
        int row = row0 + ty * 4 + i;
        int bidx = row >> 9;           // / 512
        int s    = row & 511;
        #pragma unroll
        for (int jp = 0; jp < 4; jp += 2) {
            int c = cbase + jp;                 // even
            int t = c >> 7;                     // / 128
            int r = c & 127;
            int isQ = (r < 64);
            int d = r & 63;                     // even
            float xe = acc[i][jp]     + bias[c];
            float xo = acc[i][jp + 1] + bias[c + 1];
            float cv = g_cs[(s << 6) + d];
            float sv = g_sn[(s << 6) + d];
            float ve = xe * cv - xo * sv;
            float vo = xo * cv + xe * sv;
            float* dst = (isQ ? g_q : g_k)
                       + ((size_t)((bidx * NT + t) * SEQ + s) << 6) + d;
            dst[0] = ve;
            dst[1] = vo;
        }
    }
}

// ---------------------------------------------------------------------------
// Kernel 2: logits[b,t,m,n] = sum_d q[b,t,m,d]*k[b,t,n,d], masked, /8.
// Grid (n-tiles=8, m-tiles=8, z=b*9+t=144). Block tile 64x64, K=64 full.
// ---------------------------------------------------------------------------
__global__ void __launch_bounds__(256) qk_kernel(
    const int* __restrict__ amask,
    float* __restrict__ out)
{
    __shared__ float Qt[64][68];   // [d][m]
    __shared__ float Kt[64][68];   // [d][n]

    const int z    = blockIdx.z;        // b*9 + t
    const int bidx = z / NT;
    const int n0   = blockIdx.x * 64;
    const int m0   = blockIdx.y * 64;
    const int tid  = threadIdx.x;
    const int tx   = tid & 15;
    const int ty   = tid >> 4;

    // Load 64x64 Q and K tiles, transposing into [d][row] layout.
    #pragma unroll
    for (int r = 0; r < 4; r++) {
        int e  = r * 256 + tid;
        int mm = e >> 4;
        int dq = (e & 15) * 4;
        float4 qv = *(const float4*)(g_q + ((size_t)(z * SEQ + m0 + mm) << 6) + dq);
        Qt[dq + 0][mm] = qv.x;
        Qt[dq + 1][mm] = qv.y;
        Qt[dq + 2][mm] = qv.z;
        Qt[dq + 3][mm] = qv.w;
        float4 kv = *(const float4*)(g_k + ((size_t)(z * SEQ + n0 + mm) << 6) + dq);
        Kt[dq + 0][mm] = kv.x;
        Kt[dq + 1][mm] = kv.y;
        Kt[dq + 2][mm] = kv.z;
        Kt[dq + 3][mm] = kv.w;
    }
    __syncthreads();

    float acc[4][4] = {};
    #pragma unroll 16
    for (int d = 0; d < 64; d++) {
        float4 a4 = *(const float4*)&Qt[d][ty * 4];
        float4 b4 = *(const float4*)&Kt[d][tx * 4];
        float a[4] = {a4.x, a4.y, a4.z, a4.w};
        float b[4] = {b4.x, b4.y, b4.z, b4.w};
        #pragma unroll
        for (int i = 0; i < 4; i++)
            #pragma unroll
            for (int j = 0; j < 4; j++)
                acc[i][j] += a[i] * b[j];
    }

    // Epilogue: padding mask, strict-lower-triangular mask, scale by 1/8.
    const float NEGC = 1000000000000.0f;
    float pm[4];
    #pragma unroll
    for (int j = 0; j < 4; j++)
        pm[j] = (float)amask[(bidx << 9) + n0 + tx * 4 + j];

    #pragma unroll
    for (int i = 0; i < 4; i++) {
        int m = m0 + ty * 4 + i;
        float4 o;
        float v[4];
        #pragma unroll
        for (int j = 0; j < 4; j++) {
            int n = n0 + tx * 4 + j;
            float val = acc[i][j] * pm[j] - (1.0f - pm[j]) * NEGC;
            if (m > n) val -= NEGC;     // tril(ones, -1)
            v[j] = val * 0.125f;        // / sqrt(64)
        }
        o.x = v[0]; o.y = v[1]; o.z = v[2]; o.w = v[3];
        *(float4*)(out + ((size_t)z * SEQ + m) * SEQ + n0 + tx * 4) = o;
    }
}

// ---------------------------------------------------------------------------
extern "C" void kernel_launch(void* const* d_in, const int* in_sizes, int n_in,
                              void* d_out, int out_size)
{
    const float* hidden = (const float*)d_in[0];
    const float* Wm     = (const float*)d_in[1];
    const float* bias   = (const float*)d_in[2];
    const int*   amask  = (const int*)d_in[3];
    float* out = (float*)d_out;

    rope_table<<<(SEQ * DIM + 255) / 256, 256>>>();
    gemm_rope<<<dim3(COUT / 64, MROWS / 64), 256>>>(hidden, Wm, bias);
    qk_kernel<<<dim3(SEQ / 64, SEQ / 64, BATCH * NT), 256>>>(amask, out);
}